// round 8
// baseline (speedup 1.0000x reference)
#include <cuda_runtime.h>
#include <cuda_bf16.h>
#include <cstdint>

#define NN 8192

// ---------------- scratch (device globals; no allocations) ------------------
__device__ __align__(128) uint32_t g_adjbits[(size_t)NN * 256];     // 8 MB bitmask
__device__ float g_invdeg[NN];
__device__ __align__(128) __nv_bfloat16 g_xT[(size_t)256 * NN];     // x^T bf16
__device__ __align__(128) __nv_bfloat16 g_nx_hi[(size_t)NN * 512];  // [x1|x] hi
__device__ __align__(128) __nv_bfloat16 g_nx_lo[(size_t)NN * 512];  // [x1|x] lo
__device__ __align__(128) __nv_bfloat16 g_Wt_hi[768 * 512];         // W^T hi
__device__ __align__(128) __nv_bfloat16 g_Wt_lo[768 * 512];         // W^T lo

// ---------------- helpers ----------------------------------------------------
__device__ __forceinline__ uint32_t smem_u32(const void* p) {
    uint32_t a;
    asm("{ .reg .u64 t; cvta.to.shared.u64 t, %1; cvt.u32.u64 %0, t; }"
        : "=r"(a) : "l"(p));
    return a;
}
__device__ __forceinline__ void cp16(uint32_t dst, const void* src) {
    asm volatile("cp.async.cg.shared.global [%0], [%1], 16;" :: "r"(dst), "l"(src));
}
__device__ __forceinline__ void cp_commit() {
    asm volatile("cp.async.commit_group;" ::: "memory");
}
template <int N> __device__ __forceinline__ void cp_wait() {
    asm volatile("cp.async.wait_group %0;" :: "n"(N) : "memory");
}
__device__ __forceinline__ void ldsm4(uint32_t& r0, uint32_t& r1, uint32_t& r2,
                                      uint32_t& r3, uint32_t addr) {
    asm volatile("ldmatrix.sync.aligned.m8n8.x4.shared.b16 {%0,%1,%2,%3}, [%4];"
                 : "=r"(r0), "=r"(r1), "=r"(r2), "=r"(r3) : "r"(addr));
}
__device__ __forceinline__ void mma16816(float* c, const uint32_t* a,
                                         const uint32_t* b) {
    asm volatile(
        "mma.sync.aligned.m16n8k16.row.col.f32.bf16.bf16.f32 "
        "{%0,%1,%2,%3}, {%4,%5,%6,%7}, {%8,%9}, {%0,%1,%2,%3};"
        : "+f"(c[0]), "+f"(c[1]), "+f"(c[2]), "+f"(c[3])
        : "r"(a[0]), "r"(a[1]), "r"(a[2]), "r"(a[3]), "r"(b[0]), "r"(b[1]));
}

// generic warp-tile compute for gemm2 path: 32(M) x 64(N) x (KK*16)(K)
template <int KK, int PITCH>
__device__ __forceinline__ void tile_compute(uint32_t aAddr, uint32_t bAddr,
                                             float (&c)[2][8][4]) {
#pragma unroll
    for (int kk = 0; kk < KK; ++kk) {
        uint32_t A[2][4], B[8][2];
        ldsm4(A[0][0], A[0][1], A[0][2], A[0][3], aAddr + kk * 32);
        ldsm4(A[1][0], A[1][1], A[1][2], A[1][3], aAddr + 16 * PITCH + kk * 32);
#pragma unroll
        for (int p = 0; p < 4; ++p) {
            uint32_t r0, r1, r2, r3;
            ldsm4(r0, r1, r2, r3, bAddr + p * 16 * PITCH + kk * 32);
            B[2 * p][0] = r0; B[2 * p][1] = r1;
            B[2 * p + 1][0] = r2; B[2 * p + 1][1] = r3;
        }
#pragma unroll
        for (int mt = 0; mt < 2; ++mt)
#pragma unroll
            for (int nt = 0; nt < 8; ++nt)
                mma16816(c[mt][nt], A[mt], B[nt]);
    }
}

// ---------------- conv: adj int32 -> bitmask + inv degree --------------------
__global__ void __launch_bounds__(256) k_conv(const int* __restrict__ adj) {
    __shared__ int wsum[8];
    const int row = blockIdx.x;
    const int lane = threadIdx.x & 31, w = threadIdx.x >> 5;
    const int* src = adj + (size_t)row * NN + w * 1024 + lane;
    uint32_t* dst = g_adjbits + (size_t)row * 256 + w * 32;
    int cnt = 0;
#pragma unroll 8
    for (int p = 0; p < 32; ++p) {
        int v = src[p * 32];
        uint32_t b = __ballot_sync(0xFFFFFFFFu, v == 1);
        if (lane == 0) { dst[p] = b; cnt += __popc(b); }
    }
    if (lane == 0) wsum[w] = cnt;
    __syncthreads();
    if (threadIdx.x == 0) {
        int t = 0;
#pragma unroll
        for (int i = 0; i < 8; ++i) t += wsum[i];
        g_invdeg[row] = 1.0f / (float)t;
    }
}

// ---------------- prep kernels ----------------------------------------------
__global__ void k_prep_x(const float* __restrict__ x) {
    __shared__ float tile[32][33];
    const int n0 = blockIdx.x * 32, f0 = blockIdx.y * 32;
    const int tx = threadIdx.x, ty = threadIdx.y;
    float v = x[(size_t)(n0 + ty) * 256 + f0 + tx];
    tile[ty][tx] = v;
    __nv_bfloat16 h = __float2bfloat16(v);
    size_t o = (size_t)(n0 + ty) * 512 + 256 + f0 + tx;
    g_nx_hi[o] = h;
    g_nx_lo[o] = __float2bfloat16(v - __bfloat162float(h));
    __syncthreads();
    g_xT[(size_t)(f0 + ty) * NN + n0 + tx] = __float2bfloat16(tile[tx][ty]);
}

__global__ void k_prep_w(const float* __restrict__ w) {
    const int b = blockIdx.x;            // Wt row = k*256 + o
    const int k = b >> 8, o = b & 255;
    const float* src = w + (size_t)k * 512 * 256 + o;
    __nv_bfloat16* dh = g_Wt_hi + (size_t)b * 512;
    __nv_bfloat16* dl = g_Wt_lo + (size_t)b * 512;
    for (int f = threadIdx.x; f < 512; f += 256) {
        float v = src[(size_t)f * 256];
        __nv_bfloat16 h = __float2bfloat16(v);
        dh[f] = h;
        dl[f] = __float2bfloat16(v - __bfloat162float(h));
    }
}

// ---------------- GEMM1: x1 = (adj @ x) / deg --------------------------------
// grid 128 = 64 M-tiles x 2 N-tiles, 512 threads (16 warps, 4/SMSP).
// CTA tile 128x128, warp tile 32x32. K = 8192 in 64 chunks of 128.
// A: bitmask -> register mma fragments. B: g_xT via 4-stage cp.async.
#define PITCH1 272u
#define BSTG1  34816u            // 128 * 272; 4 stages = 139264 B

__device__ __forceinline__ void g1_cpB(uint32_t sbase, int s, int kc, int n0,
                                       int tid) {
    const int n = tid >> 2, qq = tid & 3;
    const uint32_t dst = sbase + s * BSTG1 + n * PITCH1 + qq * 64;
    const char* src = (const char*)(g_xT + (size_t)(n0 + n) * NN + kc * 128) +
                      qq * 64;
#pragma unroll
    for (int j = 0; j < 4; ++j) cp16(dst + j * 16, src + j * 16);
}

__global__ void __launch_bounds__(512, 1) k_gemm1() {
    extern __shared__ char smem[];
    const uint32_t sbase = smem_u32(smem);
    const int tid = threadIdx.x, lane = tid & 31, wid = tid >> 5;
    const int wm = wid & 3, wn = wid >> 2;       // 4 x 4 warp grid
    const int m0 = (blockIdx.x >> 1) * 128, n0 = (blockIdx.x & 1) * 128;

    // bit-row pointers: rows r, r+8, r+16, r+24 of this warp's 32-row block
    const uint32_t* pr[4];
    {
        const uint32_t* base = g_adjbits + (size_t)(m0 + wm * 32 + (lane >> 2)) * 256;
        pr[0] = base; pr[1] = base + 8 * 256;
        pr[2] = base + 16 * 256; pr[3] = base + 24 * 256;
    }

    g1_cpB(sbase, 0, 0, n0, tid); cp_commit();
    g1_cpB(sbase, 1, 1, n0, tid); cp_commit();
    g1_cpB(sbase, 2, 2, n0, tid); cp_commit();

    uint32_t Wc[4][4], Wn[4][4];
#pragma unroll
    for (int rr = 0; rr < 4; ++rr)
#pragma unroll
        for (int j = 0; j < 4; ++j) Wc[rr][j] = pr[rr][j];

    const uint32_t bAddr0 = sbase +
        (wn * 32 + ((lane >> 4) << 3) + (lane & 7)) * PITCH1 + ((lane >> 3) & 1) * 16;
    const int sh0 = (lane & 3) * 2;

    float c[2][4][4] = {};
    for (int it = 0; it < 64; ++it) {
        cp_wait<2>();
        __syncthreads();
        if (it + 3 < 64) g1_cpB(sbase, (it + 3) & 3, it + 3, n0, tid);
        cp_commit();
        if (it + 1 < 64) {
#pragma unroll
            for (int rr = 0; rr < 4; ++rr)
#pragma unroll
                for (int j = 0; j < 4; ++j) Wn[rr][j] = pr[rr][(it + 1) * 4 + j];
        }
        const uint32_t bA = bAddr0 + (it & 3) * BSTG1;
#pragma unroll
        for (int kk = 0; kk < 8; ++kk) {
            uint32_t B[4][2];
#pragma unroll
            for (int p = 0; p < 2; ++p) {
                uint32_t r0, r1, r2, r3;
                ldsm4(r0, r1, r2, r3, bA + p * (16 * PITCH1) + kk * 32);
                B[2 * p][0] = r0; B[2 * p][1] = r1;
                B[2 * p + 1][0] = r2; B[2 * p + 1][1] = r3;
            }
            const int j = kk >> 1;
            const int hs = sh0 + (kk & 1) * 16;
#pragma unroll
            for (int mt = 0; mt < 2; ++mt) {
                uint32_t wr  = Wc[2 * mt][j] >> hs;
                uint32_t wr8 = Wc[2 * mt + 1][j] >> hs;
                uint32_t A[4];
                A[0] = (wr  & 1u) * 0x3F80u | ((wr  >> 1) & 1u) * 0x3F800000u;
                A[1] = (wr8 & 1u) * 0x3F80u | ((wr8 >> 1) & 1u) * 0x3F800000u;
                A[2] = ((wr  >> 8) & 1u) * 0x3F80u | ((wr  >> 9) & 1u) * 0x3F800000u;
                A[3] = ((wr8 >> 8) & 1u) * 0x3F80u | ((wr8 >> 9) & 1u) * 0x3F800000u;
#pragma unroll
                for (int nt = 0; nt < 4; ++nt) mma16816(c[mt][nt], A, B[nt]);
            }
        }
#pragma unroll
        for (int rr = 0; rr < 4; ++rr)
#pragma unroll
            for (int j2 = 0; j2 < 4; ++j2) Wc[rr][j2] = Wn[rr][j2];
    }

    // epilogue: /deg, hi/lo bf16 split into g_nx
    const int r = lane >> 2, q = lane & 3;
#pragma unroll
    for (int mt = 0; mt < 2; ++mt) {
        const int lr = wm * 32 + mt * 16 + r;
        const float inv0 = g_invdeg[m0 + lr];
        const float inv1 = g_invdeg[m0 + lr + 8];
        const size_t gm0 = (size_t)(m0 + lr), gm1 = gm0 + 8;
#pragma unroll
        for (int nt = 0; nt < 4; ++nt) {
            const int col = n0 + wn * 32 + nt * 8 + q * 2;
            float v0 = c[mt][nt][0] * inv0, v1 = c[mt][nt][1] * inv0;
            float v2 = c[mt][nt][2] * inv1, v3 = c[mt][nt][3] * inv1;
            __nv_bfloat16 h0 = __float2bfloat16(v0), h1 = __float2bfloat16(v1);
            __nv_bfloat16 h2 = __float2bfloat16(v2), h3 = __float2bfloat16(v3);
            *(uint32_t*)(g_nx_hi + gm0 * 512 + col) =
                ((uint32_t)__bfloat16_as_ushort(h1) << 16) | __bfloat16_as_ushort(h0);
            *(uint32_t*)(g_nx_hi + gm1 * 512 + col) =
                ((uint32_t)__bfloat16_as_ushort(h3) << 16) | __bfloat16_as_ushort(h2);
            __nv_bfloat16 l0 = __float2bfloat16(v0 - __bfloat162float(h0));
            __nv_bfloat16 l1 = __float2bfloat16(v1 - __bfloat162float(h1));
            __nv_bfloat16 l2 = __float2bfloat16(v2 - __bfloat162float(h2));
            __nv_bfloat16 l3 = __float2bfloat16(v3 - __bfloat162float(h3));
            *(uint32_t*)(g_nx_lo + gm0 * 512 + col) =
                ((uint32_t)__bfloat16_as_ushort(l1) << 16) | __bfloat16_as_ushort(l0);
            *(uint32_t*)(g_nx_lo + gm1 * 512 + col) =
                ((uint32_t)__bfloat16_as_ushort(l3) << 16) | __bfloat16_as_ushort(l2);
        }
    }
}

// ---------------- GEMM2: out[k] = nx @ W[k] + bias (3-term bf16 split) ------
// (unchanged: 66.6us measured)
#define ROWB   80u
#define STG    10240u
#define BOFF   40960u

__device__ __forceinline__ void g2_cp(uint32_t sbase, int s, int it, int m0,
                                      int bn0, int tid) {
    const __nv_bfloat16 *Ap, *Bp;
    int f0;
    if (it < 16)      { Ap = g_nx_hi; Bp = g_Wt_hi; f0 = it * 32; }
    else if (it < 32) { Ap = g_nx_hi; Bp = g_Wt_lo; f0 = (it - 16) * 32; }
    else              { Ap = g_nx_lo; Bp = g_Wt_hi; f0 = 256 + (it - 32) * 32; }
#pragma unroll
    for (int i = 0; i < 2; ++i) {
        int idx = tid + i * 256;
        int rr = idx >> 2, cc = idx & 3;
        cp16(sbase + s * STG + rr * ROWB + cc * 16,
             Ap + (size_t)(m0 + rr) * 512 + f0 + cc * 8);
        cp16(sbase + BOFF + s * STG + rr * ROWB + cc * 16,
             Bp + (size_t)(bn0 + rr) * 512 + f0 + cc * 8);
    }
}

__global__ void __launch_bounds__(256, 2) k_gemm2(const float* __restrict__ bias,
                                                  float* __restrict__ out) {
    extern __shared__ char smem[];
    __shared__ float sbias[128];
    const uint32_t sbase = smem_u32(smem);
    const int tid = threadIdx.x, lane = tid & 31, wid = tid >> 5;
    const int wm = wid >> 1, wn = wid & 1;
    const int bx = blockIdx.x;
    const int m0 = (bx / 6) * 128;
    const int ntile = bx % 6;
    const int kh = ntile >> 1, o0 = (ntile & 1) * 128;
    const int bn0 = kh * 256 + o0;
    if (tid < 128) sbias[tid] = bias[o0 + tid];

    g2_cp(sbase, 0, 0, m0, bn0, tid); cp_commit();
    g2_cp(sbase, 1, 1, m0, bn0, tid); cp_commit();
    g2_cp(sbase, 2, 2, m0, bn0, tid); cp_commit();

    const uint32_t aAddr0 = sbase + (wm * 32 + (lane & 15)) * ROWB + (lane >> 4) * 16;
    const uint32_t bAddr0 = sbase + BOFF +
        (wn * 64 + ((lane >> 4) << 3) + (lane & 7)) * ROWB + ((lane >> 3) & 1) * 16;

    float c[2][8][4] = {};
    for (int it = 0; it < 40; ++it) {
        const int s = it & 3;
        cp_wait<2>();
        __syncthreads();
        if (it + 3 < 40) g2_cp(sbase, (it + 3) & 3, it + 3, m0, bn0, tid);
        cp_commit();
        tile_compute<2, ROWB>(aAddr0 + s * STG, bAddr0 + s * STG, c);
    }

    const int r = lane >> 2, q = lane & 3;
#pragma unroll
    for (int mt = 0; mt < 2; ++mt) {
        const int lr = wm * 32 + mt * 16 + r;
        const size_t gm0 = (size_t)(m0 + lr);
#pragma unroll
        for (int nt = 0; nt < 8; ++nt) {
            const int oc = wn * 64 + nt * 8 + q * 2;
            float2 va = make_float2(c[mt][nt][0] + sbias[oc],
                                    c[mt][nt][1] + sbias[oc + 1]);
            float2 vb = make_float2(c[mt][nt][2] + sbias[oc],
                                    c[mt][nt][3] + sbias[oc + 1]);
            *(float2*)(out + ((size_t)kh * NN + gm0) * 256 + o0 + oc) = va;
            *(float2*)(out + ((size_t)kh * NN + gm0 + 8) * 256 + o0 + oc) = vb;
        }
    }
}

// ---------------- launch -----------------------------------------------------
extern "C" void kernel_launch(void* const* d_in, const int* in_sizes, int n_in,
                              void* d_out, int out_size) {
    const float* x = nullptr;
    const int* adj = nullptr;
    const float* w = nullptr;
    const float* bias = nullptr;
    for (int i = 0; i < n_in; ++i) {
        long sz = in_sizes[i];
        if (sz == (long)NN * 256) x = (const float*)d_in[i];
        else if (sz == (long)NN * NN) adj = (const int*)d_in[i];
        else if (sz == 3L * 512 * 256) w = (const float*)d_in[i];
        else if (sz == 256) bias = (const float*)d_in[i];
    }
    float* out = (float*)d_out;

    cudaFuncSetAttribute(k_gemm1, cudaFuncAttributeMaxDynamicSharedMemorySize, 139264);
    cudaFuncSetAttribute(k_gemm2, cudaFuncAttributeMaxDynamicSharedMemorySize, 81920);

    k_prep_x<<<dim3(256, 8), dim3(32, 32)>>>(x);
    k_prep_w<<<768, 256>>>(w);
    k_conv<<<NN, 256>>>(adj);
    k_gemm1<<<128, 512, 139264>>>();
    k_gemm2<<<384, 256, 81920>>>(bias, out);
}